// round 12
// baseline (speedup 1.0000x reference)
#include <cuda_runtime.h>
#include <cstdint>

// Instant-NGP fused forward, R12: R11 kernels + chunked cross-stream pipelining.
// N split into 8 chunks. Encode chunks serialize on the main stream; each MLP
// chunk runs on a forked stream gated by an event on its encode chunk, so
// mlp(c) overlaps encode(c+1). Encode is L2/LTS-bound, MLP is L1/tensor-bound
// -> complementary resources when co-resident.

constexpr int NLV = 16;
constexpr int TSZ = 1 << 19;
constexpr unsigned PRIME_Y = 2654435761u;
constexpr int N_MAX = 4194304;
constexpr int NCHUNK = 8;

__device__ float g_feat[(size_t)N_MAX * 32];   // 512 MB scratch

__device__ __forceinline__ uint32_t f2tf(float f) {
    uint32_t u; asm("cvt.rna.tf32.f32 %0, %1;" : "=r"(u) : "f"(f)); return u;
}

__device__ __forceinline__ void mma8(float c[4], const uint32_t a[4], const uint32_t b[2]) {
    asm volatile("mma.sync.aligned.m16n8k8.row.col.f32.tf32.tf32.f32 "
                 "{%0,%1,%2,%3},{%4,%5,%6,%7},{%8,%9},{%0,%1,%2,%3};"
                 : "+f"(c[0]), "+f"(c[1]), "+f"(c[2]), "+f"(c[3])
                 : "r"(a[0]), "r"(a[1]), "r"(a[2]), "r"(a[3]), "r"(b[0]), "r"(b[1]));
}

__device__ __forceinline__ void ldsm4(uint32_t r[4], uint32_t addr) {
    asm volatile("ldmatrix.sync.aligned.m8n8.x4.shared.b16 {%0,%1,%2,%3}, [%4];"
                 : "=r"(r[0]), "=r"(r[1]), "=r"(r[2]), "=r"(r[3]) : "r"(addr));
}

// ======================= Kernel A: encode =======================
__global__ __launch_bounds__(256) void ngp_encode(
    const float* __restrict__ pos,
    const float* __restrict__ table,
    int start, int n)
{
    const int idx  = start + blockIdx.x * 256 + threadIdx.x;
    if (idx >= n) return;
    const int lane = idx & 31;
    float* dst = g_feat + ((size_t)(idx >> 5) << 10) + lane;

    const float2 p = ((const float2*)pos)[idx];

#pragma unroll
    for (int lp = 0; lp < 8; lp++) {
        unsigned ix[2][4];
        float wgt[2][2];
#pragma unroll
        for (int l2 = 0; l2 < 2; l2++) {
            const int lvl = lp * 2 + l2;
            const int res = 16 << lvl;
            const float scale = (float)(res - 1);
            float px = p.x * scale + 0.5f;
            float py = p.y * scale + 0.5f;
            float fx = floorf(px), fy = floorf(py);
            wgt[l2][0] = px - fx;
            wgt[l2][1] = py - fy;
            unsigned cx = (unsigned)fx, cy = (unsigned)fy;
            if ((long long)res * res <= TSZ) {
                unsigned i00 = cx + cy * (unsigned)res;
                ix[l2][0] = i00;
                ix[l2][1] = i00 + 1u;
                ix[l2][2] = i00 + (unsigned)res;
                ix[l2][3] = i00 + (unsigned)res + 1u;
            } else {
                unsigned hy0 = cy * PRIME_Y;
                unsigned hy1 = (cy + 1u) * PRIME_Y;
                ix[l2][0] = (cx        ^ hy0) & (unsigned)(TSZ - 1);
                ix[l2][1] = ((cx + 1u) ^ hy0) & (unsigned)(TSZ - 1);
                ix[l2][2] = (cx        ^ hy1) & (unsigned)(TSZ - 1);
                ix[l2][3] = ((cx + 1u) ^ hy1) & (unsigned)(TSZ - 1);
            }
        }
        float2 v[2][4];
#pragma unroll
        for (int l2 = 0; l2 < 2; l2++) {
            const float2* tl = (const float2*)table + (size_t)(lp * 2 + l2) * TSZ;
#pragma unroll
            for (int c = 0; c < 4; c++) v[l2][c] = __ldg(tl + ix[l2][c]);
        }
#pragma unroll
        for (int l2 = 0; l2 < 2; l2++) {
            const int lvl = lp * 2 + l2;
            float wx = wgt[l2][0], wy = wgt[l2][1];
            float w00 = (1.f - wx) * (1.f - wy);
            float w10 = wx * (1.f - wy);
            float w01 = (1.f - wx) * wy;
            float w11 = wx * wy;
            float f0 = w00 * v[l2][0].x + w10 * v[l2][1].x + w01 * v[l2][2].x + w11 * v[l2][3].x;
            float f1 = w00 * v[l2][0].y + w10 * v[l2][1].y + w01 * v[l2][2].y + w11 * v[l2][3].y;
            dst[(2 * lvl + 0) * 32] = __uint_as_float(f2tf(f0));
            dst[(2 * lvl + 1) * 32] = __uint_as_float(f2tf(f1));
        }
    }
}

// ======================= Kernel B: MLP (tiled) =======================
constexpr int SA_STR = 33;
constexpr int SC_STR = 68;
constexpr int SW2_STR = 68;
constexpr int WBLK   = 32 * SC_STR;
constexpr int TILES  = 4;
constexpr int CTA_PTS = 128 * TILES;  // 512
constexpr int SMEM_BYTES = (4 * WBLK + 64 * SW2_STR) * 4;   // 52224

__global__ __launch_bounds__(128, 4) void ngp_mlp(
    const float* __restrict__ W1,
    const float* __restrict__ W2,
    const float* __restrict__ W3,
    float* __restrict__ out,
    int start, int n)
{
    extern __shared__ float sm[];
    float* sW2T = sm + 4 * WBLK;

    const int t    = threadIdx.x;
    const int lane = t & 31;
    const int warp = t >> 5;
    const int g    = lane >> 2;
    const int q    = lane & 3;

    float* sW = sm + warp * WBLK;

    for (int i = t; i < 64 * 64; i += 128) {
        int k = i >> 6, c = i & 63;
        sW2T[c * SW2_STR + k] = __uint_as_float(f2tf(W2[i]));
    }
    __syncthreads();

    const uint32_t sw_u32   = (uint32_t)__cvta_generic_to_shared(sW);
    const uint32_t sw2t_u32 = (uint32_t)__cvta_generic_to_shared(sW2T);
    const int m_ = lane >> 3;
    const int r8 = lane & 7;
    const uint32_t aaddr0 = sw_u32 + ((r8 + 8 * (m_ & 1)) * SC_STR + 4 * (m_ >> 1)) * 4;
    const uint32_t aaddr1 = aaddr0 + 16 * SC_STR * 4;
    const uint32_t baddr  = sw2t_u32 + (((m_ >> 1) * 8 + r8) * SW2_STR + 4 * (m_ & 1)) * 4;

    const int warp_base = start + blockIdx.x * CTA_PTS + warp * (32 * TILES);

    for (int tt = 0; tt < TILES; tt++) {
        const int pbase = warp_base + tt * 32;
        if (pbase >= n) break;

        {
            const float4* src = (const float4*)(g_feat + ((size_t)(pbase >> 5) << 10));
#pragma unroll
            for (int j = 0; j < 8; j++) {
                int i4 = j * 32 + lane;
                float4 v = __ldg(src + i4);
                int k = i4 >> 3;
                int r = (i4 & 7) * 4;
                float* d = sW + k * SA_STR + r;
                d[0] = v.x; d[1] = v.y; d[2] = v.z; d[3] = v.w;
            }
        }
        __syncwarp();

        float acc[2][8][4];
#pragma unroll
        for (int mt = 0; mt < 2; mt++)
#pragma unroll
            for (int nt = 0; nt < 8; nt++)
#pragma unroll
                for (int r = 0; r < 4; r++) acc[mt][nt][r] = 0.f;

#pragma unroll
        for (int k0 = 0; k0 < 32; k0 += 8) {
            uint32_t a[2][4];
#pragma unroll
            for (int mt = 0; mt < 2; mt++) {
                int lr = mt * 16 + g;
                a[mt][0] = __float_as_uint(sW[(k0 + q) * SA_STR + lr]);
                a[mt][1] = __float_as_uint(sW[(k0 + q) * SA_STR + lr + 8]);
                a[mt][2] = __float_as_uint(sW[(k0 + q + 4) * SA_STR + lr]);
                a[mt][3] = __float_as_uint(sW[(k0 + q + 4) * SA_STR + lr + 8]);
            }
#pragma unroll
            for (int nt = 0; nt < 8; nt++) {
                uint32_t b[2];
                b[0] = f2tf(__ldg(&W1[(k0 + q)     * 64 + nt * 8 + g]));
                b[1] = f2tf(__ldg(&W1[(k0 + q + 4) * 64 + nt * 8 + g]));
                mma8(acc[0][nt], a[0], b);
                mma8(acc[1][nt], a[1], b);
            }
        }
        __syncwarp();

#pragma unroll
        for (int mt = 0; mt < 2; mt++) {
            int lr = mt * 16 + g;
#pragma unroll
            for (int nt = 0; nt < 8; nt++) {
                int c = nt * 8 + 2 * q;
                sW[lr * SC_STR + c]           = __uint_as_float(f2tf(fmaxf(acc[mt][nt][0], 0.f)));
                sW[lr * SC_STR + c + 1]       = __uint_as_float(f2tf(fmaxf(acc[mt][nt][1], 0.f)));
                sW[(lr + 8) * SC_STR + c]     = __uint_as_float(f2tf(fmaxf(acc[mt][nt][2], 0.f)));
                sW[(lr + 8) * SC_STR + c + 1] = __uint_as_float(f2tf(fmaxf(acc[mt][nt][3], 0.f)));
            }
        }
        __syncwarp();

        float acc2[2][8][4];
#pragma unroll
        for (int mt = 0; mt < 2; mt++)
#pragma unroll
            for (int nt = 0; nt < 8; nt++)
#pragma unroll
                for (int r = 0; r < 4; r++) acc2[mt][nt][r] = 0.f;

#pragma unroll
        for (int k0 = 0; k0 < 64; k0 += 8) {
            uint32_t a0r[4], a1r[4];
            ldsm4(a0r, aaddr0 + k0 * 4);
            ldsm4(a1r, aaddr1 + k0 * 4);
#pragma unroll
            for (int nt0 = 0; nt0 < 8; nt0 += 2) {
                uint32_t br[4];
                ldsm4(br, baddr + (nt0 * 8 * SW2_STR + k0) * 4);
                mma8(acc2[0][nt0],     a0r, &br[0]);
                mma8(acc2[1][nt0],     a1r, &br[0]);
                mma8(acc2[0][nt0 + 1], a0r, &br[2]);
                mma8(acc2[1][nt0 + 1], a1r, &br[2]);
            }
        }

        float o[2][2][3];
#pragma unroll
        for (int mt = 0; mt < 2; mt++)
#pragma unroll
            for (int h = 0; h < 2; h++)
#pragma unroll
                for (int j = 0; j < 3; j++) o[mt][h][j] = 0.f;

#pragma unroll
        for (int nt = 0; nt < 8; nt++) {
            int c0 = nt * 8 + 2 * q;
            float w30[3], w31[3];
#pragma unroll
            for (int j = 0; j < 3; j++) {
                w30[j] = __ldg(&W3[c0 * 3 + j]);
                w31[j] = __ldg(&W3[(c0 + 1) * 3 + j]);
            }
#pragma unroll
            for (int mt = 0; mt < 2; mt++) {
                float v0 = fmaxf(acc2[mt][nt][0], 0.f);
                float v1 = fmaxf(acc2[mt][nt][1], 0.f);
                float v2 = fmaxf(acc2[mt][nt][2], 0.f);
                float v3 = fmaxf(acc2[mt][nt][3], 0.f);
#pragma unroll
                for (int j = 0; j < 3; j++) {
                    o[mt][0][j] += v0 * w30[j] + v1 * w31[j];
                    o[mt][1][j] += v2 * w30[j] + v3 * w31[j];
                }
            }
        }

#pragma unroll
        for (int mt = 0; mt < 2; mt++)
#pragma unroll
            for (int h = 0; h < 2; h++)
#pragma unroll
                for (int j = 0; j < 3; j++) {
                    float v = o[mt][h][j];
                    v += __shfl_xor_sync(0xffffffffu, v, 1);
                    v += __shfl_xor_sync(0xffffffffu, v, 2);
                    o[mt][h][j] = v;
                }

        if (q < 3) {
            int j = q;
#pragma unroll
            for (int mt = 0; mt < 2; mt++)
#pragma unroll
                for (int h = 0; h < 2; h++) {
                    int row = pbase + mt * 16 + g + h * 8;
                    if (row < n) out[row * 3 + j] = o[mt][h][j];
                }
        }
        __syncwarp();
    }
}

extern "C" void kernel_launch(void* const* d_in, const int* in_sizes, int n_in,
                              void* d_out, int out_size) {
    const float* pos   = (const float*)d_in[0];
    const float* table = (const float*)d_in[1];
    const float* W1    = (const float*)d_in[2];
    const float* W2    = (const float*)d_in[3];
    const float* W3    = (const float*)d_in[4];
    float* out = (float*)d_out;
    int n = in_sizes[0] / 2;

    static bool inited = false;
    static cudaStream_t sB;
    static cudaEvent_t evFork, evJoin, evE[NCHUNK];
    if (!inited) {
        cudaFuncSetAttribute(ngp_mlp, cudaFuncAttributeMaxDynamicSharedMemorySize,
                             SMEM_BYTES);
        cudaStreamCreateWithFlags(&sB, cudaStreamNonBlocking);
        cudaEventCreateWithFlags(&evFork, cudaEventDisableTiming);
        cudaEventCreateWithFlags(&evJoin, cudaEventDisableTiming);
        for (int c = 0; c < NCHUNK; c++)
            cudaEventCreateWithFlags(&evE[c], cudaEventDisableTiming);
        inited = true;
    }

    // chunk boundaries: multiples of CTA_PTS (512)
    int per = ((n + NCHUNK - 1) / NCHUNK + CTA_PTS - 1) / CTA_PTS * CTA_PTS;

    // fork sB into the capture graph
    cudaEventRecord(evFork, 0);
    cudaStreamWaitEvent(sB, evFork, 0);

    for (int c = 0; c < NCHUNK; c++) {
        int start = c * per;
        if (start >= n) break;
        int cnt = (start + per <= n) ? per : (n - start);

        ngp_encode<<<(cnt + 255) / 256, 256, 0, 0>>>(pos, table, start, n);
        cudaEventRecord(evE[c], 0);
        cudaStreamWaitEvent(sB, evE[c], 0);
        ngp_mlp<<<(cnt + CTA_PTS - 1) / CTA_PTS, 128, SMEM_BYTES, sB>>>(
            W1, W2, W3, out, start, n);
    }

    // join sB back into the main stream
    cudaEventRecord(evJoin, sB);
    cudaStreamWaitEvent(0, evJoin, 0);
}

// round 14
// speedup vs baseline: 2.1560x; 2.1560x over previous
#include <cuda_runtime.h>
#include <cstdint>

// Instant-NGP fused forward, R14: R13 with the W3-staging bug fixed (the
// `if (t<192)` guard under blockDim=128 left sW3[128..191] unstaged).
// Kernel A (encode): unchanged (gather/LTS-bound, ~640us).
// Kernel B (MLP): W1T (stride 36), W2T (stride 68), W3 staged in smem once
// per CTA; both GEMMs' B-fragments via ldmatrix. TILES=8 (1024 pts/CTA).

constexpr int NLV = 16;
constexpr int TSZ = 1 << 19;
constexpr unsigned PRIME_Y = 2654435761u;
constexpr int N_MAX = 4194304;

__device__ float g_feat[(size_t)N_MAX * 32];   // 512 MB scratch

__device__ __forceinline__ uint32_t f2tf(float f) {
    uint32_t u; asm("cvt.rna.tf32.f32 %0, %1;" : "=r"(u) : "f"(f)); return u;
}

__device__ __forceinline__ void mma8(float c[4], const uint32_t a[4], const uint32_t b[2]) {
    asm volatile("mma.sync.aligned.m16n8k8.row.col.f32.tf32.tf32.f32 "
                 "{%0,%1,%2,%3},{%4,%5,%6,%7},{%8,%9},{%0,%1,%2,%3};"
                 : "+f"(c[0]), "+f"(c[1]), "+f"(c[2]), "+f"(c[3])
                 : "r"(a[0]), "r"(a[1]), "r"(a[2]), "r"(a[3]), "r"(b[0]), "r"(b[1]));
}

__device__ __forceinline__ void ldsm4(uint32_t r[4], uint32_t addr) {
    asm volatile("ldmatrix.sync.aligned.m8n8.x4.shared.b16 {%0,%1,%2,%3}, [%4];"
                 : "=r"(r[0]), "=r"(r[1]), "=r"(r[2]), "=r"(r[3]) : "r"(addr));
}

// ======================= Kernel A: encode (unchanged) ===============
__global__ __launch_bounds__(256) void ngp_encode(
    const float* __restrict__ pos,
    const float* __restrict__ table,
    int n)
{
    const int idx  = blockIdx.x * 256 + threadIdx.x;
    if (idx >= n) return;
    const int lane = idx & 31;
    float* dst = g_feat + ((size_t)(idx >> 5) << 10) + lane;

    const float2 p = ((const float2*)pos)[idx];

#pragma unroll
    for (int lp = 0; lp < 8; lp++) {
        unsigned ix[2][4];
        float wgt[2][2];
#pragma unroll
        for (int l2 = 0; l2 < 2; l2++) {
            const int lvl = lp * 2 + l2;
            const int res = 16 << lvl;
            const float scale = (float)(res - 1);
            float px = p.x * scale + 0.5f;
            float py = p.y * scale + 0.5f;
            float fx = floorf(px), fy = floorf(py);
            wgt[l2][0] = px - fx;
            wgt[l2][1] = py - fy;
            unsigned cx = (unsigned)fx, cy = (unsigned)fy;
            if ((long long)res * res <= TSZ) {
                unsigned i00 = cx + cy * (unsigned)res;
                ix[l2][0] = i00;
                ix[l2][1] = i00 + 1u;
                ix[l2][2] = i00 + (unsigned)res;
                ix[l2][3] = i00 + (unsigned)res + 1u;
            } else {
                unsigned hy0 = cy * PRIME_Y;
                unsigned hy1 = (cy + 1u) * PRIME_Y;
                ix[l2][0] = (cx        ^ hy0) & (unsigned)(TSZ - 1);
                ix[l2][1] = ((cx + 1u) ^ hy0) & (unsigned)(TSZ - 1);
                ix[l2][2] = (cx        ^ hy1) & (unsigned)(TSZ - 1);
                ix[l2][3] = ((cx + 1u) ^ hy1) & (unsigned)(TSZ - 1);
            }
        }
        float2 v[2][4];
#pragma unroll
        for (int l2 = 0; l2 < 2; l2++) {
            const float2* tl = (const float2*)table + (size_t)(lp * 2 + l2) * TSZ;
#pragma unroll
            for (int c = 0; c < 4; c++) v[l2][c] = __ldg(tl + ix[l2][c]);
        }
#pragma unroll
        for (int l2 = 0; l2 < 2; l2++) {
            const int lvl = lp * 2 + l2;
            float wx = wgt[l2][0], wy = wgt[l2][1];
            float w00 = (1.f - wx) * (1.f - wy);
            float w10 = wx * (1.f - wy);
            float w01 = (1.f - wx) * wy;
            float w11 = wx * wy;
            float f0 = w00 * v[l2][0].x + w10 * v[l2][1].x + w01 * v[l2][2].x + w11 * v[l2][3].x;
            float f1 = w00 * v[l2][0].y + w10 * v[l2][1].y + w01 * v[l2][2].y + w11 * v[l2][3].y;
            dst[(2 * lvl + 0) * 32] = __uint_as_float(f2tf(f0));
            dst[(2 * lvl + 1) * 32] = __uint_as_float(f2tf(f1));
        }
    }
}

// ======================= Kernel B: MLP (tiled, fully staged) ===============
constexpr int SA_STR  = 33;            // sA[k][row]
constexpr int SC_STR  = 68;            // sC[row][k], 272B rows
constexpr int SW2_STR = 68;            // W2T[n][k]
constexpr int SW1_STR = 36;            // W1T[n][k], 144B rows (16B-aligned)
constexpr int WBLK    = 32 * SC_STR;   // 2176 floats/warp (sA aliases low part)
constexpr int TILES   = 8;
constexpr int CTA_PTS = 128 * TILES;   // 1024
constexpr int SMEM_FLOATS = 4 * WBLK + 64 * SW2_STR + 64 * SW1_STR + 192;
constexpr int SMEM_BYTES  = SMEM_FLOATS * 4;   // 62208

__global__ __launch_bounds__(128, 3) void ngp_mlp(
    const float* __restrict__ W1,
    const float* __restrict__ W2,
    const float* __restrict__ W3,
    float* __restrict__ out,
    int n)
{
    extern __shared__ float sm[];
    float* sW2T = sm + 4 * WBLK;                 // [64][68]
    float* sW1T = sW2T + 64 * SW2_STR;           // [64][36]
    float* sW3  = sW1T + 64 * SW1_STR;           // [192]

    const int t    = threadIdx.x;
    const int lane = t & 31;
    const int warp = t >> 5;
    const int g    = lane >> 2;
    const int q    = lane & 3;

    float* sW = sm + warp * WBLK;

    // ---- stage weights ONCE per CTA ----
    for (int i = t; i < 64 * 64; i += 128) {
        int k = i >> 6, c = i & 63;
        sW2T[c * SW2_STR + k] = __uint_as_float(f2tf(W2[i]));
    }
    for (int i = t; i < 32 * 64; i += 128) {
        int k = i >> 6, c = i & 63;
        sW1T[c * SW1_STR + k] = __uint_as_float(f2tf(W1[i]));
    }
    for (int i = t; i < 192; i += 128) sW3[i] = W3[i];   // FIX: strided (was if t<192)
    __syncthreads();

    // hoisted ldmatrix bases
    const uint32_t sw_u32   = (uint32_t)__cvta_generic_to_shared(sW);
    const uint32_t sw2t_u32 = (uint32_t)__cvta_generic_to_shared(sW2T);
    const uint32_t sw1t_u32 = (uint32_t)__cvta_generic_to_shared(sW1T);
    const int m_ = lane >> 3;
    const int r8 = lane & 7;
    const uint32_t aaddr0 = sw_u32 + ((r8 + 8 * (m_ & 1)) * SC_STR + 4 * (m_ >> 1)) * 4;
    const uint32_t aaddr1 = aaddr0 + 16 * SC_STR * 4;
    const uint32_t b2addr = sw2t_u32 + (((m_ >> 1) * 8 + r8) * SW2_STR + 4 * (m_ & 1)) * 4;
    const uint32_t b1addr = sw1t_u32 + (((m_ >> 1) * 8 + r8) * SW1_STR + 4 * (m_ & 1)) * 4;

    const int warp_base = blockIdx.x * CTA_PTS + warp * (32 * TILES);

    for (int tt = 0; tt < TILES; tt++) {
        const int pbase = warp_base + tt * 32;
        if (pbase >= n) break;

        // ---- feat copy -> sA [k][row] ----
        {
            const float4* src = (const float4*)(g_feat + ((size_t)(pbase >> 5) << 10));
#pragma unroll
            for (int j = 0; j < 8; j++) {
                int i4 = j * 32 + lane;
                float4 v = __ldg(src + i4);
                int k = i4 >> 3;
                int r = (i4 & 7) * 4;
                float* d = sW + k * SA_STR + r;
                d[0] = v.x; d[1] = v.y; d[2] = v.z; d[3] = v.w;
            }
        }
        __syncwarp();

        // ---- GEMM1: C1[32x64] = A[32x32] @ W1[32x64] (B via ldmatrix) ----
        float acc[2][8][4];
#pragma unroll
        for (int mt = 0; mt < 2; mt++)
#pragma unroll
            for (int nt = 0; nt < 8; nt++)
#pragma unroll
                for (int r = 0; r < 4; r++) acc[mt][nt][r] = 0.f;

#pragma unroll
        for (int k0 = 0; k0 < 32; k0 += 8) {
            uint32_t a[2][4];
#pragma unroll
            for (int mt = 0; mt < 2; mt++) {
                int lr = mt * 16 + g;
                a[mt][0] = __float_as_uint(sW[(k0 + q) * SA_STR + lr]);
                a[mt][1] = __float_as_uint(sW[(k0 + q) * SA_STR + lr + 8]);
                a[mt][2] = __float_as_uint(sW[(k0 + q + 4) * SA_STR + lr]);
                a[mt][3] = __float_as_uint(sW[(k0 + q + 4) * SA_STR + lr + 8]);
            }
#pragma unroll
            for (int nt0 = 0; nt0 < 8; nt0 += 2) {
                uint32_t br[4];
                ldsm4(br, b1addr + (nt0 * 8 * SW1_STR + k0) * 4);
                mma8(acc[0][nt0],     a[0], &br[0]);
                mma8(acc[1][nt0],     a[1], &br[0]);
                mma8(acc[0][nt0 + 1], a[0], &br[2]);
                mma8(acc[1][nt0 + 1], a[1], &br[2]);
            }
        }
        __syncwarp();

        // ---- ReLU + store C1 -> sC [row][k] ----
#pragma unroll
        for (int mt = 0; mt < 2; mt++) {
            int lr = mt * 16 + g;
#pragma unroll
            for (int nt = 0; nt < 8; nt++) {
                int c = nt * 8 + 2 * q;
                sW[lr * SC_STR + c]           = __uint_as_float(f2tf(fmaxf(acc[mt][nt][0], 0.f)));
                sW[lr * SC_STR + c + 1]       = __uint_as_float(f2tf(fmaxf(acc[mt][nt][1], 0.f)));
                sW[(lr + 8) * SC_STR + c]     = __uint_as_float(f2tf(fmaxf(acc[mt][nt][2], 0.f)));
                sW[(lr + 8) * SC_STR + c + 1] = __uint_as_float(f2tf(fmaxf(acc[mt][nt][3], 0.f)));
            }
        }
        __syncwarp();

        // ---- GEMM2 via ldmatrix (A and B) ----
        float acc2[2][8][4];
#pragma unroll
        for (int mt = 0; mt < 2; mt++)
#pragma unroll
            for (int nt = 0; nt < 8; nt++)
#pragma unroll
                for (int r = 0; r < 4; r++) acc2[mt][nt][r] = 0.f;

#pragma unroll
        for (int k0 = 0; k0 < 64; k0 += 8) {
            uint32_t a0r[4], a1r[4];
            ldsm4(a0r, aaddr0 + k0 * 4);
            ldsm4(a1r, aaddr1 + k0 * 4);
#pragma unroll
            for (int nt0 = 0; nt0 < 8; nt0 += 2) {
                uint32_t br[4];
                ldsm4(br, b2addr + (nt0 * 8 * SW2_STR + k0) * 4);
                mma8(acc2[0][nt0],     a0r, &br[0]);
                mma8(acc2[1][nt0],     a1r, &br[0]);
                mma8(acc2[0][nt0 + 1], a0r, &br[2]);
                mma8(acc2[1][nt0 + 1], a1r, &br[2]);
            }
        }

        // ---- epilogue: ReLU + layer3 (W3 from smem) + quad reduce ----
        float o[2][2][3];
#pragma unroll
        for (int mt = 0; mt < 2; mt++)
#pragma unroll
            for (int h = 0; h < 2; h++)
#pragma unroll
                for (int j = 0; j < 3; j++) o[mt][h][j] = 0.f;

#pragma unroll
        for (int nt = 0; nt < 8; nt++) {
            int c0 = nt * 8 + 2 * q;
            float w30[3], w31[3];
#pragma unroll
            for (int j = 0; j < 3; j++) {
                w30[j] = sW3[c0 * 3 + j];
                w31[j] = sW3[(c0 + 1) * 3 + j];
            }
#pragma unroll
            for (int mt = 0; mt < 2; mt++) {
                float v0 = fmaxf(acc2[mt][nt][0], 0.f);
                float v1 = fmaxf(acc2[mt][nt][1], 0.f);
                float v2 = fmaxf(acc2[mt][nt][2], 0.f);
                float v3 = fmaxf(acc2[mt][nt][3], 0.f);
#pragma unroll
                for (int j = 0; j < 3; j++) {
                    o[mt][0][j] += v0 * w30[j] + v1 * w31[j];
                    o[mt][1][j] += v2 * w30[j] + v3 * w31[j];
                }
            }
        }

#pragma unroll
        for (int mt = 0; mt < 2; mt++)
#pragma unroll
            for (int h = 0; h < 2; h++)
#pragma unroll
                for (int j = 0; j < 3; j++) {
                    float v = o[mt][h][j];
                    v += __shfl_xor_sync(0xffffffffu, v, 1);
                    v += __shfl_xor_sync(0xffffffffu, v, 2);
                    o[mt][h][j] = v;
                }

        if (q < 3) {
            int j = q;
#pragma unroll
            for (int mt = 0; mt < 2; mt++)
#pragma unroll
                for (int h = 0; h < 2; h++) {
                    int row = pbase + mt * 16 + g + h * 8;
                    if (row < n) out[row * 3 + j] = o[mt][h][j];
                }
        }
        __syncwarp();
    }
}

extern "C" void kernel_launch(void* const* d_in, const int* in_sizes, int n_in,
                              void* d_out, int out_size) {
    const float* pos   = (const float*)d_in[0];
    const float* table = (const float*)d_in[1];
    const float* W1    = (const float*)d_in[2];
    const float* W2    = (const float*)d_in[3];
    const float* W3    = (const float*)d_in[4];
    float* out = (float*)d_out;
    int n = in_sizes[0] / 2;

    static bool attr_set = false;
    if (!attr_set) {
        cudaFuncSetAttribute(ngp_mlp, cudaFuncAttributeMaxDynamicSharedMemorySize,
                             SMEM_BYTES);
        attr_set = true;
    }

    ngp_encode<<<(n + 255) / 256, 256>>>(pos, table, n);
    ngp_mlp<<<(n + CTA_PTS - 1) / CTA_PTS, 128, SMEM_BYTES>>>(W1, W2, W3, out, n);
}

// round 15
// speedup vs baseline: 2.1794x; 1.0109x over previous
#include <cuda_runtime.h>
#include <cstdint>

// Instant-NGP fused forward, R15: R14 + 4-level gather batching in encode
// (16 independent loads in flight per issue group; standalone encode kernel
// has no accumulator pressure so the batching arrays fit in registers).
// MLP kernel unchanged from R14 (369us, tensor=46%).

constexpr int NLV = 16;
constexpr int TSZ = 1 << 19;
constexpr unsigned PRIME_Y = 2654435761u;
constexpr int N_MAX = 4194304;

__device__ float g_feat[(size_t)N_MAX * 32];   // 512 MB scratch

__device__ __forceinline__ uint32_t f2tf(float f) {
    uint32_t u; asm("cvt.rna.tf32.f32 %0, %1;" : "=r"(u) : "f"(f)); return u;
}

__device__ __forceinline__ void mma8(float c[4], const uint32_t a[4], const uint32_t b[2]) {
    asm volatile("mma.sync.aligned.m16n8k8.row.col.f32.tf32.tf32.f32 "
                 "{%0,%1,%2,%3},{%4,%5,%6,%7},{%8,%9},{%0,%1,%2,%3};"
                 : "+f"(c[0]), "+f"(c[1]), "+f"(c[2]), "+f"(c[3])
                 : "r"(a[0]), "r"(a[1]), "r"(a[2]), "r"(a[3]), "r"(b[0]), "r"(b[1]));
}

__device__ __forceinline__ void ldsm4(uint32_t r[4], uint32_t addr) {
    asm volatile("ldmatrix.sync.aligned.m8n8.x4.shared.b16 {%0,%1,%2,%3}, [%4];"
                 : "=r"(r[0]), "=r"(r[1]), "=r"(r[2]), "=r"(r[3]) : "r"(addr));
}

// ======================= Kernel A: encode (4-level batching) ===============
__global__ __launch_bounds__(256) void ngp_encode(
    const float* __restrict__ pos,
    const float* __restrict__ table,
    int n)
{
    const int idx  = blockIdx.x * 256 + threadIdx.x;
    if (idx >= n) return;
    const int lane = idx & 31;
    float* dst = g_feat + ((size_t)(idx >> 5) << 10) + lane;

    const float2 p = ((const float2*)pos)[idx];

#pragma unroll
    for (int lg = 0; lg < 4; lg++) {
        unsigned ix[4][4];
        float wgt[4][2];
        // phase 1: addresses + weights for 4 levels
#pragma unroll
        for (int l4 = 0; l4 < 4; l4++) {
            const int lvl = lg * 4 + l4;
            const int res = 16 << lvl;
            const float scale = (float)(res - 1);
            float px = p.x * scale + 0.5f;
            float py = p.y * scale + 0.5f;
            float fx = floorf(px), fy = floorf(py);
            wgt[l4][0] = px - fx;
            wgt[l4][1] = py - fy;
            unsigned cx = (unsigned)fx, cy = (unsigned)fy;
            if ((long long)res * res <= TSZ) {
                unsigned i00 = cx + cy * (unsigned)res;
                ix[l4][0] = i00;
                ix[l4][1] = i00 + 1u;
                ix[l4][2] = i00 + (unsigned)res;
                ix[l4][3] = i00 + (unsigned)res + 1u;
            } else {
                unsigned hy0 = cy * PRIME_Y;
                unsigned hy1 = (cy + 1u) * PRIME_Y;
                ix[l4][0] = (cx        ^ hy0) & (unsigned)(TSZ - 1);
                ix[l4][1] = ((cx + 1u) ^ hy0) & (unsigned)(TSZ - 1);
                ix[l4][2] = (cx        ^ hy1) & (unsigned)(TSZ - 1);
                ix[l4][3] = ((cx + 1u) ^ hy1) & (unsigned)(TSZ - 1);
            }
        }
        // phase 2: issue all 16 independent gathers
        float2 v[4][4];
#pragma unroll
        for (int l4 = 0; l4 < 4; l4++) {
            const float2* tl = (const float2*)table + (size_t)(lg * 4 + l4) * TSZ;
#pragma unroll
            for (int c = 0; c < 4; c++) v[l4][c] = __ldg(tl + ix[l4][c]);
        }
        // phase 3: bilinear + coalesced store
#pragma unroll
        for (int l4 = 0; l4 < 4; l4++) {
            const int lvl = lg * 4 + l4;
            float wx = wgt[l4][0], wy = wgt[l4][1];
            float w00 = (1.f - wx) * (1.f - wy);
            float w10 = wx * (1.f - wy);
            float w01 = (1.f - wx) * wy;
            float w11 = wx * wy;
            float f0 = w00 * v[l4][0].x + w10 * v[l4][1].x + w01 * v[l4][2].x + w11 * v[l4][3].x;
            float f1 = w00 * v[l4][0].y + w10 * v[l4][1].y + w01 * v[l4][2].y + w11 * v[l4][3].y;
            dst[(2 * lvl + 0) * 32] = __uint_as_float(f2tf(f0));
            dst[(2 * lvl + 1) * 32] = __uint_as_float(f2tf(f1));
        }
    }
}

// ======================= Kernel B: MLP (unchanged from R14) ===============
constexpr int SA_STR  = 33;
constexpr int SC_STR  = 68;
constexpr int SW2_STR = 68;
constexpr int SW1_STR = 36;
constexpr int WBLK    = 32 * SC_STR;
constexpr int TILES   = 8;
constexpr int CTA_PTS = 128 * TILES;   // 1024
constexpr int SMEM_FLOATS = 4 * WBLK + 64 * SW2_STR + 64 * SW1_STR + 192;
constexpr int SMEM_BYTES  = SMEM_FLOATS * 4;   // 62208

__global__ __launch_bounds__(128, 3) void ngp_mlp(
    const float* __restrict__ W1,
    const float* __restrict__ W2,
    const float* __restrict__ W3,
    float* __restrict__ out,
    int n)
{
    extern __shared__ float sm[];
    float* sW2T = sm + 4 * WBLK;
    float* sW1T = sW2T + 64 * SW2_STR;
    float* sW3  = sW1T + 64 * SW1_STR;

    const int t    = threadIdx.x;
    const int lane = t & 31;
    const int warp = t >> 5;
    const int g    = lane >> 2;
    const int q    = lane & 3;

    float* sW = sm + warp * WBLK;

    for (int i = t; i < 64 * 64; i += 128) {
        int k = i >> 6, c = i & 63;
        sW2T[c * SW2_STR + k] = __uint_as_float(f2tf(W2[i]));
    }
    for (int i = t; i < 32 * 64; i += 128) {
        int k = i >> 6, c = i & 63;
        sW1T[c * SW1_STR + k] = __uint_as_float(f2tf(W1[i]));
    }
    for (int i = t; i < 192; i += 128) sW3[i] = W3[i];
    __syncthreads();

    const uint32_t sw_u32   = (uint32_t)__cvta_generic_to_shared(sW);
    const uint32_t sw2t_u32 = (uint32_t)__cvta_generic_to_shared(sW2T);
    const uint32_t sw1t_u32 = (uint32_t)__cvta_generic_to_shared(sW1T);
    const int m_ = lane >> 3;
    const int r8 = lane & 7;
    const uint32_t aaddr0 = sw_u32 + ((r8 + 8 * (m_ & 1)) * SC_STR + 4 * (m_ >> 1)) * 4;
    const uint32_t aaddr1 = aaddr0 + 16 * SC_STR * 4;
    const uint32_t b2addr = sw2t_u32 + (((m_ >> 1) * 8 + r8) * SW2_STR + 4 * (m_ & 1)) * 4;
    const uint32_t b1addr = sw1t_u32 + (((m_ >> 1) * 8 + r8) * SW1_STR + 4 * (m_ & 1)) * 4;

    const int warp_base = blockIdx.x * CTA_PTS + warp * (32 * TILES);

    for (int tt = 0; tt < TILES; tt++) {
        const int pbase = warp_base + tt * 32;
        if (pbase >= n) break;

        {
            const float4* src = (const float4*)(g_feat + ((size_t)(pbase >> 5) << 10));
#pragma unroll
            for (int j = 0; j < 8; j++) {
                int i4 = j * 32 + lane;
                float4 v = __ldg(src + i4);
                int k = i4 >> 3;
                int r = (i4 & 7) * 4;
                float* d = sW + k * SA_STR + r;
                d[0] = v.x; d[1] = v.y; d[2] = v.z; d[3] = v.w;
            }
        }
        __syncwarp();

        float acc[2][8][4];
#pragma unroll
        for (int mt = 0; mt < 2; mt++)
#pragma unroll
            for (int nt = 0; nt < 8; nt++)
#pragma unroll
                for (int r = 0; r < 4; r++) acc[mt][nt][r] = 0.f;

#pragma unroll
        for (int k0 = 0; k0 < 32; k0 += 8) {
            uint32_t a[2][4];
#pragma unroll
            for (int mt = 0; mt < 2; mt++) {
                int lr = mt * 16 + g;
                a[mt][0] = __float_as_uint(sW[(k0 + q) * SA_STR + lr]);
                a[mt][1] = __float_as_uint(sW[(k0 + q) * SA_STR + lr + 8]);
                a[mt][2] = __float_as_uint(sW[(k0 + q + 4) * SA_STR + lr]);
                a[mt][3] = __float_as_uint(sW[(k0 + q + 4) * SA_STR + lr + 8]);
            }
#pragma unroll
            for (int nt0 = 0; nt0 < 8; nt0 += 2) {
                uint32_t br[4];
                ldsm4(br, b1addr + (nt0 * 8 * SW1_STR + k0) * 4);
                mma8(acc[0][nt0],     a[0], &br[0]);
                mma8(acc[1][nt0],     a[1], &br[0]);
                mma8(acc[0][nt0 + 1], a[0], &br[2]);
                mma8(acc[1][nt0 + 1], a[1], &br[2]);
            }
        }
        __syncwarp();

#pragma unroll
        for (int mt = 0; mt < 2; mt++) {
            int lr = mt * 16 + g;
#pragma unroll
            for (int nt = 0; nt < 8; nt++) {
                int c = nt * 8 + 2 * q;
                sW[lr * SC_STR + c]           = __uint_as_float(f2tf(fmaxf(acc[mt][nt][0], 0.f)));
                sW[lr * SC_STR + c + 1]       = __uint_as_float(f2tf(fmaxf(acc[mt][nt][1], 0.f)));
                sW[(lr + 8) * SC_STR + c]     = __uint_as_float(f2tf(fmaxf(acc[mt][nt][2], 0.f)));
                sW[(lr + 8) * SC_STR + c + 1] = __uint_as_float(f2tf(fmaxf(acc[mt][nt][3], 0.f)));
            }
        }
        __syncwarp();

        float acc2[2][8][4];
#pragma unroll
        for (int mt = 0; mt < 2; mt++)
#pragma unroll
            for (int nt = 0; nt < 8; nt++)
#pragma unroll
                for (int r = 0; r < 4; r++) acc2[mt][nt][r] = 0.f;

#pragma unroll
        for (int k0 = 0; k0 < 64; k0 += 8) {
            uint32_t a0r[4], a1r[4];
            ldsm4(a0r, aaddr0 + k0 * 4);
            ldsm4(a1r, aaddr1 + k0 * 4);
#pragma unroll
            for (int nt0 = 0; nt0 < 8; nt0 += 2) {
                uint32_t br[4];
                ldsm4(br, b2addr + (nt0 * 8 * SW2_STR + k0) * 4);
                mma8(acc2[0][nt0],     a0r, &br[0]);
                mma8(acc2[1][nt0],     a1r, &br[0]);
                mma8(acc2[0][nt0 + 1], a0r, &br[2]);
                mma8(acc2[1][nt0 + 1], a1r, &br[2]);
            }
        }

        float o[2][2][3];
#pragma unroll
        for (int mt = 0; mt < 2; mt++)
#pragma unroll
            for (int h = 0; h < 2; h++)
#pragma unroll
                for (int j = 0; j < 3; j++) o[mt][h][j] = 0.f;

#pragma unroll
        for (int nt = 0; nt < 8; nt++) {
            int c0 = nt * 8 + 2 * q;
            float w30[3], w31[3];
#pragma unroll
            for (int j = 0; j < 3; j++) {
                w30[j] = sW3[c0 * 3 + j];
                w31[j] = sW3[(c0 + 1) * 3 + j];
            }
#pragma unroll
            for (int mt = 0; mt < 2; mt++) {
                float v0 = fmaxf(acc2[mt][nt][0], 0.f);
                float v1 = fmaxf(acc2[mt][nt][1], 0.f);
                float v2 = fmaxf(acc2[mt][nt][2], 0.f);
                float v3 = fmaxf(acc2[mt][nt][3], 0.f);
#pragma unroll
                for (int j = 0; j < 3; j++) {
                    o[mt][0][j] += v0 * w30[j] + v1 * w31[j];
                    o[mt][1][j] += v2 * w30[j] + v3 * w31[j];
                }
            }
        }

#pragma unroll
        for (int mt = 0; mt < 2; mt++)
#pragma unroll
            for (int h = 0; h < 2; h++)
#pragma unroll
                for (int j = 0; j < 3; j++) {
                    float v = o[mt][h][j];
                    v += __shfl_xor_sync(0xffffffffu, v, 1);
                    v += __shfl_xor_sync(0xffffffffu, v, 2);
                    o[mt][h][j] = v;
                }

        if (q < 3) {
            int j = q;
#pragma unroll
            for (int mt = 0; mt < 2; mt++)
#pragma unroll
                for (int h = 0; h < 2; h++) {
                    int row = pbase + mt * 16 + g + h * 8;
                    if (row < n) out[row * 3 + j] = o[mt][h][j];
                }
        }
        __syncwarp();
    }
}

extern "C" void kernel_launch(void* const* d_in, const int* in_sizes, int n_in,
                              void* d_out, int out_size) {
    const float* pos   = (const float*)d_in[0];
    const float* table = (const float*)d_in[1];
    const float* W1    = (const float*)d_in[2];
    const float* W2    = (const float*)d_in[3];
    const float* W3    = (const float*)d_in[4];
    float* out = (float*)d_out;
    int n = in_sizes[0] / 2;

    static bool attr_set = false;
    if (!attr_set) {
        cudaFuncSetAttribute(ngp_mlp, cudaFuncAttributeMaxDynamicSharedMemorySize,
                             SMEM_BYTES);
        attr_set = true;
    }

    ngp_encode<<<(n + 255) / 256, 256>>>(pos, table, n);
    ngp_mlp<<<(n + CTA_PTS - 1) / CTA_PTS, 128, SMEM_BYTES>>>(W1, W2, W3, out, n);
}

// round 16
// speedup vs baseline: 2.2243x; 1.0206x over previous
#include <cuda_runtime.h>
#include <cstdint>

// Instant-NGP fused forward, R16: R15 + vectorized MLP smem traffic.
// (1) C1 ReLU stores as float2 (64->32 STS/lane/tile);
// (2) epilogue W3 reads as 3x float2 (48->24 LDS);
// (3) SA_STR 33->36 so feat-copy stores are STS.128 (32->8 stores).
// Encode unchanged (at its LTS floor ~630us).

constexpr int NLV = 16;
constexpr int TSZ = 1 << 19;
constexpr unsigned PRIME_Y = 2654435761u;
constexpr int N_MAX = 4194304;

__device__ float g_feat[(size_t)N_MAX * 32];   // 512 MB scratch

__device__ __forceinline__ uint32_t f2tf(float f) {
    uint32_t u; asm("cvt.rna.tf32.f32 %0, %1;" : "=r"(u) : "f"(f)); return u;
}

__device__ __forceinline__ void mma8(float c[4], const uint32_t a[4], const uint32_t b[2]) {
    asm volatile("mma.sync.aligned.m16n8k8.row.col.f32.tf32.tf32.f32 "
                 "{%0,%1,%2,%3},{%4,%5,%6,%7},{%8,%9},{%0,%1,%2,%3};"
                 : "+f"(c[0]), "+f"(c[1]), "+f"(c[2]), "+f"(c[3])
                 : "r"(a[0]), "r"(a[1]), "r"(a[2]), "r"(a[3]), "r"(b[0]), "r"(b[1]));
}

__device__ __forceinline__ void ldsm4(uint32_t r[4], uint32_t addr) {
    asm volatile("ldmatrix.sync.aligned.m8n8.x4.shared.b16 {%0,%1,%2,%3}, [%4];"
                 : "=r"(r[0]), "=r"(r[1]), "=r"(r[2]), "=r"(r[3]) : "r"(addr));
}

// ======================= Kernel A: encode (unchanged) ===============
__global__ __launch_bounds__(256) void ngp_encode(
    const float* __restrict__ pos,
    const float* __restrict__ table,
    int n)
{
    const int idx  = blockIdx.x * 256 + threadIdx.x;
    if (idx >= n) return;
    const int lane = idx & 31;
    float* dst = g_feat + ((size_t)(idx >> 5) << 10) + lane;

    const float2 p = ((const float2*)pos)[idx];

#pragma unroll
    for (int lg = 0; lg < 4; lg++) {
        unsigned ix[4][4];
        float wgt[4][2];
#pragma unroll
        for (int l4 = 0; l4 < 4; l4++) {
            const int lvl = lg * 4 + l4;
            const int res = 16 << lvl;
            const float scale = (float)(res - 1);
            float px = p.x * scale + 0.5f;
            float py = p.y * scale + 0.5f;
            float fx = floorf(px), fy = floorf(py);
            wgt[l4][0] = px - fx;
            wgt[l4][1] = py - fy;
            unsigned cx = (unsigned)fx, cy = (unsigned)fy;
            if ((long long)res * res <= TSZ) {
                unsigned i00 = cx + cy * (unsigned)res;
                ix[l4][0] = i00;
                ix[l4][1] = i00 + 1u;
                ix[l4][2] = i00 + (unsigned)res;
                ix[l4][3] = i00 + (unsigned)res + 1u;
            } else {
                unsigned hy0 = cy * PRIME_Y;
                unsigned hy1 = (cy + 1u) * PRIME_Y;
                ix[l4][0] = (cx        ^ hy0) & (unsigned)(TSZ - 1);
                ix[l4][1] = ((cx + 1u) ^ hy0) & (unsigned)(TSZ - 1);
                ix[l4][2] = (cx        ^ hy1) & (unsigned)(TSZ - 1);
                ix[l4][3] = ((cx + 1u) ^ hy1) & (unsigned)(TSZ - 1);
            }
        }
        float2 v[4][4];
#pragma unroll
        for (int l4 = 0; l4 < 4; l4++) {
            const float2* tl = (const float2*)table + (size_t)(lg * 4 + l4) * TSZ;
#pragma unroll
            for (int c = 0; c < 4; c++) v[l4][c] = __ldg(tl + ix[l4][c]);
        }
#pragma unroll
        for (int l4 = 0; l4 < 4; l4++) {
            const int lvl = lg * 4 + l4;
            float wx = wgt[l4][0], wy = wgt[l4][1];
            float w00 = (1.f - wx) * (1.f - wy);
            float w10 = wx * (1.f - wy);
            float w01 = (1.f - wx) * wy;
            float w11 = wx * wy;
            float f0 = w00 * v[l4][0].x + w10 * v[l4][1].x + w01 * v[l4][2].x + w11 * v[l4][3].x;
            float f1 = w00 * v[l4][0].y + w10 * v[l4][1].y + w01 * v[l4][2].y + w11 * v[l4][3].y;
            dst[(2 * lvl + 0) * 32] = __uint_as_float(f2tf(f0));
            dst[(2 * lvl + 1) * 32] = __uint_as_float(f2tf(f1));
        }
    }
}

// ======================= Kernel B: MLP =======================
constexpr int SA_STR  = 36;            // [k][row]; k*36+r 16B-aligned; banks 4q+g CF
constexpr int SC_STR  = 68;            // [row][k], 272B rows
constexpr int SW2_STR = 68;
constexpr int SW1_STR = 36;
constexpr int WBLK    = 32 * SC_STR;   // sA (32*36=1152) aliases low part of 2176
constexpr int TILES   = 8;
constexpr int CTA_PTS = 128 * TILES;   // 1024
constexpr int SMEM_FLOATS = 4 * WBLK + 64 * SW2_STR + 64 * SW1_STR + 192;
constexpr int SMEM_BYTES  = SMEM_FLOATS * 4;   // 62208

__global__ __launch_bounds__(128, 3) void ngp_mlp(
    const float* __restrict__ W1,
    const float* __restrict__ W2,
    const float* __restrict__ W3,
    float* __restrict__ out,
    int n)
{
    extern __shared__ float sm[];
    float* sW2T = sm + 4 * WBLK;
    float* sW1T = sW2T + 64 * SW2_STR;
    float* sW3  = sW1T + 64 * SW1_STR;

    const int t    = threadIdx.x;
    const int lane = t & 31;
    const int warp = t >> 5;
    const int g    = lane >> 2;
    const int q    = lane & 3;

    float* sW = sm + warp * WBLK;

    for (int i = t; i < 64 * 64; i += 128) {
        int k = i >> 6, c = i & 63;
        sW2T[c * SW2_STR + k] = __uint_as_float(f2tf(W2[i]));
    }
    for (int i = t; i < 32 * 64; i += 128) {
        int k = i >> 6, c = i & 63;
        sW1T[c * SW1_STR + k] = __uint_as_float(f2tf(W1[i]));
    }
    for (int i = t; i < 192; i += 128) sW3[i] = W3[i];
    __syncthreads();

    const uint32_t sw_u32   = (uint32_t)__cvta_generic_to_shared(sW);
    const uint32_t sw2t_u32 = (uint32_t)__cvta_generic_to_shared(sW2T);
    const uint32_t sw1t_u32 = (uint32_t)__cvta_generic_to_shared(sW1T);
    const int m_ = lane >> 3;
    const int r8 = lane & 7;
    const uint32_t aaddr0 = sw_u32 + ((r8 + 8 * (m_ & 1)) * SC_STR + 4 * (m_ >> 1)) * 4;
    const uint32_t aaddr1 = aaddr0 + 16 * SC_STR * 4;
    const uint32_t b2addr = sw2t_u32 + (((m_ >> 1) * 8 + r8) * SW2_STR + 4 * (m_ & 1)) * 4;
    const uint32_t b1addr = sw1t_u32 + (((m_ >> 1) * 8 + r8) * SW1_STR + 4 * (m_ & 1)) * 4;

    const int warp_base = blockIdx.x * CTA_PTS + warp * (32 * TILES);

    for (int tt = 0; tt < TILES; tt++) {
        const int pbase = warp_base + tt * 32;
        if (pbase >= n) break;

        // ---- feat copy -> sA [k][row] (STS.128, 16B-aligned via SA_STR=36) ----
        {
            const float4* src = (const float4*)(g_feat + ((size_t)(pbase >> 5) << 10));
#pragma unroll
            for (int j = 0; j < 8; j++) {
                int i4 = j * 32 + lane;
                float4 v = __ldg(src + i4);
                int k = i4 >> 3;
                int r = (i4 & 7) * 4;
                *(float4*)(sW + k * SA_STR + r) = v;
            }
        }
        __syncwarp();

        // ---- GEMM1: C1[32x64] = A[32x32] @ W1[32x64] ----
        float acc[2][8][4];
#pragma unroll
        for (int mt = 0; mt < 2; mt++)
#pragma unroll
            for (int nt = 0; nt < 8; nt++)
#pragma unroll
                for (int r = 0; r < 4; r++) acc[mt][nt][r] = 0.f;

#pragma unroll
        for (int k0 = 0; k0 < 32; k0 += 8) {
            uint32_t a[2][4];
#pragma unroll
            for (int mt = 0; mt < 2; mt++) {
                int lr = mt * 16 + g;
                a[mt][0] = __float_as_uint(sW[(k0 + q) * SA_STR + lr]);
                a[mt][1] = __float_as_uint(sW[(k0 + q) * SA_STR + lr + 8]);
                a[mt][2] = __float_as_uint(sW[(k0 + q + 4) * SA_STR + lr]);
                a[mt][3] = __float_as_uint(sW[(k0 + q + 4) * SA_STR + lr + 8]);
            }
#pragma unroll
            for (int nt0 = 0; nt0 < 8; nt0 += 2) {
                uint32_t br[4];
                ldsm4(br, b1addr + (nt0 * 8 * SW1_STR + k0) * 4);
                mma8(acc[0][nt0],     a[0], &br[0]);
                mma8(acc[1][nt0],     a[1], &br[0]);
                mma8(acc[0][nt0 + 1], a[0], &br[2]);
                mma8(acc[1][nt0 + 1], a[1], &br[2]);
            }
        }
        __syncwarp();

        // ---- ReLU + store C1 -> sC [row][k] as float2 pairs ----
#pragma unroll
        for (int mt = 0; mt < 2; mt++) {
            int lr = mt * 16 + g;
#pragma unroll
            for (int nt = 0; nt < 8; nt++) {
                int c = nt * 8 + 2 * q;
                float2 lo, hi;
                lo.x = __uint_as_float(f2tf(fmaxf(acc[mt][nt][0], 0.f)));
                lo.y = __uint_as_float(f2tf(fmaxf(acc[mt][nt][1], 0.f)));
                hi.x = __uint_as_float(f2tf(fmaxf(acc[mt][nt][2], 0.f)));
                hi.y = __uint_as_float(f2tf(fmaxf(acc[mt][nt][3], 0.f)));
                *(float2*)(sW + lr * SC_STR + c)       = lo;
                *(float2*)(sW + (lr + 8) * SC_STR + c) = hi;
            }
        }
        __syncwarp();

        // ---- GEMM2 via ldmatrix (A and B) ----
        float acc2[2][8][4];
#pragma unroll
        for (int mt = 0; mt < 2; mt++)
#pragma unroll
            for (int nt = 0; nt < 8; nt++)
#pragma unroll
                for (int r = 0; r < 4; r++) acc2[mt][nt][r] = 0.f;

#pragma unroll
        for (int k0 = 0; k0 < 64; k0 += 8) {
            uint32_t a0r[4], a1r[4];
            ldsm4(a0r, aaddr0 + k0 * 4);
            ldsm4(a1r, aaddr1 + k0 * 4);
#pragma unroll
            for (int nt0 = 0; nt0 < 8; nt0 += 2) {
                uint32_t br[4];
                ldsm4(br, b2addr + (nt0 * 8 * SW2_STR + k0) * 4);
                mma8(acc2[0][nt0],     a0r, &br[0]);
                mma8(acc2[1][nt0],     a1r, &br[0]);
                mma8(acc2[0][nt0 + 1], a0r, &br[2]);
                mma8(acc2[1][nt0 + 1], a1r, &br[2]);
            }
        }

        // ---- epilogue: ReLU + layer3 (W3 via float2 x3) + quad reduce ----
        float o[2][2][3];
#pragma unroll
        for (int mt = 0; mt < 2; mt++)
#pragma unroll
            for (int h = 0; h < 2; h++)
#pragma unroll
                for (int j = 0; j < 3; j++) o[mt][h][j] = 0.f;

#pragma unroll
        for (int nt = 0; nt < 8; nt++) {
            int c0 = nt * 8 + 2 * q;           // even -> 8B-aligned base
            const float2* w6 = (const float2*)(sW3 + c0 * 3);
            float2 p0 = w6[0], p1 = w6[1], p2 = w6[2];
            float w30[3] = {p0.x, p0.y, p1.x};
            float w31[3] = {p1.y, p2.x, p2.y};
#pragma unroll
            for (int mt = 0; mt < 2; mt++) {
                float v0 = fmaxf(acc2[mt][nt][0], 0.f);
                float v1 = fmaxf(acc2[mt][nt][1], 0.f);
                float v2 = fmaxf(acc2[mt][nt][2], 0.f);
                float v3 = fmaxf(acc2[mt][nt][3], 0.f);
#pragma unroll
                for (int j = 0; j < 3; j++) {
                    o[mt][0][j] += v0 * w30[j] + v1 * w31[j];
                    o[mt][1][j] += v2 * w30[j] + v3 * w31[j];
                }
            }
        }

#pragma unroll
        for (int mt = 0; mt < 2; mt++)
#pragma unroll
            for (int h = 0; h < 2; h++)
#pragma unroll
                for (int j = 0; j < 3; j++) {
                    float v = o[mt][h][j];
                    v += __shfl_xor_sync(0xffffffffu, v, 1);
                    v += __shfl_xor_sync(0xffffffffu, v, 2);
                    o[mt][h][j] = v;
                }

        if (q < 3) {
            int j = q;
#pragma unroll
            for (int mt = 0; mt < 2; mt++)
#pragma unroll
                for (int h = 0; h < 2; h++) {
                    int row = pbase + mt * 16 + g + h * 8;
                    if (row < n) out[row * 3 + j] = o[mt][h][j];
                }
        }
        __syncwarp();
    }
}

extern "C" void kernel_launch(void* const* d_in, const int* in_sizes, int n_in,
                              void* d_out, int out_size) {
    const float* pos   = (const float*)d_in[0];
    const float* table = (const float*)d_in[1];
    const float* W1    = (const float*)d_in[2];
    const float* W2    = (const float*)d_in[3];
    const float* W3    = (const float*)d_in[4];
    float* out = (float*)d_out;
    int n = in_sizes[0] / 2;

    static bool attr_set = false;
    if (!attr_set) {
        cudaFuncSetAttribute(ngp_mlp, cudaFuncAttributeMaxDynamicSharedMemorySize,
                             SMEM_BYTES);
        attr_set = true;
    }

    ngp_encode<<<(n + 255) / 256, 256>>>(pos, table, n);
    ngp_mlp<<<(n + CTA_PTS - 1) / CTA_PTS, 128, SMEM_BYTES>>>(W1, W2, W3, out, n);
}

// round 17
// speedup vs baseline: 2.4824x; 1.1160x over previous
#include <cuda_runtime.h>
#include <cuda_fp16.h>
#include <cstdint>

// Instant-NGP fused forward, R17: fp16 MLP (mma.m16n8k16.f16, f32 accum).
// fp16 mantissa (10b) == tf32 mantissa -> same accuracy class, but K=16/mma,
// 2-byte operands everywhere: mma count, smem traffic, and g_feat scratch all
// halve. smem 33.5KB static -> launch_bounds(128,4).
// Encode: unchanged except stores half2 feats (256MB scratch, coalesced).

constexpr int NLV = 16;
constexpr int TSZ = 1 << 19;
constexpr unsigned PRIME_Y = 2654435761u;
constexpr int N_MAX = 4194304;

__device__ float g_feat[(size_t)N_MAX * 16];   // 256 MB scratch (half2 feats)

__device__ __forceinline__ void mma16(float c[4], const uint32_t a[4], const uint32_t b[2]) {
    asm volatile("mma.sync.aligned.m16n8k16.row.col.f32.f16.f16.f32 "
                 "{%0,%1,%2,%3},{%4,%5,%6,%7},{%8,%9},{%0,%1,%2,%3};"
                 : "+f"(c[0]), "+f"(c[1]), "+f"(c[2]), "+f"(c[3])
                 : "r"(a[0]), "r"(a[1]), "r"(a[2]), "r"(a[3]), "r"(b[0]), "r"(b[1]));
}

__device__ __forceinline__ void ldsm4(uint32_t r[4], uint32_t addr) {
    asm volatile("ldmatrix.sync.aligned.m8n8.x4.shared.b16 {%0,%1,%2,%3}, [%4];"
                 : "=r"(r[0]), "=r"(r[1]), "=r"(r[2]), "=r"(r[3]) : "r"(addr));
}

// ======================= Kernel A: encode ===============
__global__ __launch_bounds__(256) void ngp_encode(
    const float* __restrict__ pos,
    const float* __restrict__ table,
    int n)
{
    const int idx  = blockIdx.x * 256 + threadIdx.x;
    if (idx >= n) return;
    const int lane = idx & 31;
    // layout: [tile][lvl][lane] half2 ; 512 half2 per 32-point tile
    half2* dst = (half2*)g_feat + (((size_t)(idx >> 5)) << 9) + lane;

    const float2 p = ((const float2*)pos)[idx];

#pragma unroll
    for (int lg = 0; lg < 4; lg++) {
        unsigned ix[4][4];
        float wgt[4][2];
#pragma unroll
        for (int l4 = 0; l4 < 4; l4++) {
            const int lvl = lg * 4 + l4;
            const int res = 16 << lvl;
            const float scale = (float)(res - 1);
            float px = p.x * scale + 0.5f;
            float py = p.y * scale + 0.5f;
            float fx = floorf(px), fy = floorf(py);
            wgt[l4][0] = px - fx;
            wgt[l4][1] = py - fy;
            unsigned cx = (unsigned)fx, cy = (unsigned)fy;
            if ((long long)res * res <= TSZ) {
                unsigned i00 = cx + cy * (unsigned)res;
                ix[l4][0] = i00;
                ix[l4][1] = i00 + 1u;
                ix[l4][2] = i00 + (unsigned)res;
                ix[l4][3] = i00 + (unsigned)res + 1u;
            } else {
                unsigned hy0 = cy * PRIME_Y;
                unsigned hy1 = (cy + 1u) * PRIME_Y;
                ix[l4][0] = (cx        ^ hy0) & (unsigned)(TSZ - 1);
                ix[l4][1] = ((cx + 1u) ^ hy0) & (unsigned)(TSZ - 1);
                ix[l4][2] = (cx        ^ hy1) & (unsigned)(TSZ - 1);
                ix[l4][3] = ((cx + 1u) ^ hy1) & (unsigned)(TSZ - 1);
            }
        }
        float2 v[4][4];
#pragma unroll
        for (int l4 = 0; l4 < 4; l4++) {
            const float2* tl = (const float2*)table + (size_t)(lg * 4 + l4) * TSZ;
#pragma unroll
            for (int c = 0; c < 4; c++) v[l4][c] = __ldg(tl + ix[l4][c]);
        }
#pragma unroll
        for (int l4 = 0; l4 < 4; l4++) {
            const int lvl = lg * 4 + l4;
            float wx = wgt[l4][0], wy = wgt[l4][1];
            float w00 = (1.f - wx) * (1.f - wy);
            float w10 = wx * (1.f - wy);
            float w01 = (1.f - wx) * wy;
            float w11 = wx * wy;
            float f0 = w00 * v[l4][0].x + w10 * v[l4][1].x + w01 * v[l4][2].x + w11 * v[l4][3].x;
            float f1 = w00 * v[l4][0].y + w10 * v[l4][1].y + w01 * v[l4][2].y + w11 * v[l4][3].y;
            dst[lvl * 32] = __floats2half2_rn(f0, f1);
        }
    }
}

// ======================= Kernel B: MLP (fp16 tensor) =======================
constexpr int SA_STR  = 36;    // words; sA[k2][row], bank=(4q+g) conflict-free
constexpr int SCH_STR = 72;    // halfs; sC[row][k], 144B rows (9*16 -> ldsm CF)
constexpr int W2H_STR = 72;    // halfs; W2T[n][k]
constexpr int W1H_STR = 40;    // halfs; W1T[n][k], 80B rows (5*16 -> ldsm CF)
constexpr int WBLK    = 1152;  // words/warp: sC = 32*72 halfs = 4608B (sA aliases)
constexpr int TILES   = 8;
constexpr int CTA_PTS = 128 * TILES;   // 1024

__global__ __launch_bounds__(128, 4) void ngp_mlp(
    const float* __restrict__ W1,
    const float* __restrict__ W2,
    const float* __restrict__ W3,
    float* __restrict__ out,
    int n)
{
    __shared__ float sm[4 * WBLK];          // 18432 B (per-warp act blocks)
    __shared__ half  sW2Th[64 * W2H_STR];   // 9216 B
    __shared__ half  sW1Th[64 * W1H_STR];   // 5120 B
    __shared__ float sW3[192];              // 768 B

    const int t    = threadIdx.x;
    const int lane = t & 31;
    const int warp = t >> 5;
    const int g    = lane >> 2;
    const int q    = lane & 3;

    float* sW  = sm + warp * WBLK;          // sA view: word [k2*36 + row]
    half*  sCh = (half*)sW;                 // sC view: half [row*72 + k]

    // ---- stage weights (fp16) once per CTA ----
    for (int i = t; i < 64 * 64; i += 128)
        sW2Th[(i & 63) * W2H_STR + (i >> 6)] = __float2half(W2[i]);
    for (int i = t; i < 32 * 64; i += 128)
        sW1Th[(i & 63) * W1H_STR + (i >> 6)] = __float2half(W1[i]);
    for (int i = t; i < 192; i += 128) sW3[i] = W3[i];
    __syncthreads();

    // hoisted ldmatrix bases (byte addresses in shared space)
    const uint32_t sc_u32  = (uint32_t)__cvta_generic_to_shared(sCh);
    const uint32_t w2_u32  = (uint32_t)__cvta_generic_to_shared(sW2Th);
    const uint32_t w1_u32  = (uint32_t)__cvta_generic_to_shared(sW1Th);
    const int m_ = lane >> 3;
    const int r8 = lane & 7;
    // A (sC): r0=(rows0-7,k0-7) r1=(rows8-15,k0-7) r2=(rows0-7,k8-15) r3=(rows8-15,k8-15)
    const uint32_t aaddr = sc_u32 + (((m_ & 1) * 8 + r8) * SCH_STR + (m_ >> 1) * 8) * 2;
    // B (W1T/W2T): r0=(n0,k0-7) r1=(n0,k8-15) r2=(n0+8,k0-7) r3=(n0+8,k8-15)
    const uint32_t b1addr = w1_u32 + (((m_ >> 1) * 8 + r8) * W1H_STR + (m_ & 1) * 8) * 2;
    const uint32_t b2addr = w2_u32 + (((m_ >> 1) * 8 + r8) * W2H_STR + (m_ & 1) * 8) * 2;

    const int warp_base = blockIdx.x * CTA_PTS + warp * (32 * TILES);

    for (int tt = 0; tt < TILES; tt++) {
        const int pbase = warp_base + tt * 32;
        if (pbase >= n) break;

        // ---- feat copy: 2KB/tile -> sA [k2][row] (STS.128, conflict-free) ----
        {
            const float4* src = (const float4*)(g_feat + (((size_t)(pbase >> 5)) << 9));
#pragma unroll
            for (int j = 0; j < 4; j++) {
                int c = j * 32 + lane;             // 16B chunk id (0..127)
                float4 v = __ldg(src + c);
                int lvl = c >> 3;                  // k2 index
                int lgrp = (c & 7) * 4;            // lane group
                *(float4*)(sW + lvl * SA_STR + lgrp) = v;
            }
        }
        __syncwarp();

        // ---- GEMM1: C1[32x64] = A[32x32] @ W1[32x64], 2 k16-steps ----
        float acc[2][8][4];
#pragma unroll
        for (int mt = 0; mt < 2; mt++)
#pragma unroll
            for (int nt = 0; nt < 8; nt++)
#pragma unroll
                for (int r = 0; r < 4; r++) acc[mt][nt][r] = 0.f;

#pragma unroll
        for (int ks = 0; ks < 2; ks++) {
            uint32_t a[2][4];
#pragma unroll
            for (int mt = 0; mt < 2; mt++) {
                int lr = mt * 16 + g;
                a[mt][0] = __float_as_uint(sW[(ks * 8 + q) * SA_STR + lr]);
                a[mt][1] = __float_as_uint(sW[(ks * 8 + q) * SA_STR + lr + 8]);
                a[mt][2] = __float_as_uint(sW[(ks * 8 + q + 4) * SA_STR + lr]);
                a[mt][3] = __float_as_uint(sW[(ks * 8 + q + 4) * SA_STR + lr + 8]);
            }
#pragma unroll
            for (int nt0 = 0; nt0 < 8; nt0 += 2) {
                uint32_t br[4];
                ldsm4(br, b1addr + nt0 * 8 * W1H_STR * 2 + ks * 32);
                mma16(acc[0][nt0],     a[0], &br[0]);
                mma16(acc[1][nt0],     a[1], &br[0]);
                mma16(acc[0][nt0 + 1], a[0], &br[2]);
                mma16(acc[1][nt0 + 1], a[1], &br[2]);
            }
        }
        __syncwarp();

        // ---- ReLU + store C1 (half2) -> sC [row][k] ----
#pragma unroll
        for (int mt = 0; mt < 2; mt++) {
            int lr = mt * 16 + g;
#pragma unroll
            for (int nt = 0; nt < 8; nt++) {
                int c = nt * 8 + 2 * q;
                *(half2*)(sCh + lr * SCH_STR + c) =
                    __floats2half2_rn(fmaxf(acc[mt][nt][0], 0.f), fmaxf(acc[mt][nt][1], 0.f));
                *(half2*)(sCh + (lr + 8) * SCH_STR + c) =
                    __floats2half2_rn(fmaxf(acc[mt][nt][2], 0.f), fmaxf(acc[mt][nt][3], 0.f));
            }
        }
        __syncwarp();

        // ---- GEMM2: C2[32x64] = C1[32x64] @ W2[64x64], 4 k16-steps ----
        float acc2[2][8][4];
#pragma unroll
        for (int mt = 0; mt < 2; mt++)
#pragma unroll
            for (int nt = 0; nt < 8; nt++)
#pragma unroll
                for (int r = 0; r < 4; r++) acc2[mt][nt][r] = 0.f;

#pragma unroll
        for (int ks = 0; ks < 4; ks++) {
            uint32_t a0r[4], a1r[4];
            ldsm4(a0r, aaddr + ks * 32);
            ldsm4(a1r, aaddr + 16 * SCH_STR * 2 + ks * 32);
#pragma unroll
            for (int nt0 = 0; nt0 < 8; nt0 += 2) {
                uint32_t br[4];
                ldsm4(br, b2addr + nt0 * 8 * W2H_STR * 2 + ks * 32);
                mma16(acc2[0][nt0],     a0r, &br[0]);
                mma16(acc2[1][nt0],     a1r, &br[0]);
                mma16(acc2[0][nt0 + 1], a0r, &br[2]);
                mma16(acc2[1][nt0 + 1], a1r, &br[2]);
            }
        }

        // ---- epilogue: ReLU + layer3 (f32) + quad reduce ----
        float o[2][2][3];
#pragma unroll
        for (int mt = 0; mt < 2; mt++)
#pragma unroll
            for (int h = 0; h < 2; h++)
#pragma unroll
                for (int j = 0; j < 3; j++) o[mt][h][j] = 0.f;

#pragma unroll
        for (int nt = 0; nt < 8; nt++) {
            int c0 = nt * 8 + 2 * q;
            const float2* w6 = (const float2*)(sW3 + c0 * 3);
            float2 p0 = w6[0], p1 = w6[1], p2 = w6[2];
            float w30[3] = {p0.x, p0.y, p1.x};
            float w31[3] = {p1.y, p2.x, p2.y};
#pragma unroll
            for (int mt = 0; mt < 2; mt++) {
                float v0 = fmaxf(acc2[mt][nt][0], 0.f);
                float v1 = fmaxf(acc2[mt][nt][1], 0.f);
                float v2 = fmaxf(acc2[mt][nt][2], 0.f);
                float v3 = fmaxf(acc2[mt][nt][3], 0.f);
#pragma unroll
                for (int j = 0; j < 3; j++) {
                    o[mt][0][j] += v0 * w30[j] + v1 * w31[j];
                    o[mt][1][j] += v2 * w30[j] + v3 * w31[j];
                }
            }
        }

#pragma unroll
        for (int mt = 0; mt < 2; mt++)
#pragma unroll
            for (int h = 0; h < 2; h++)
#pragma unroll
                for (int j = 0; j < 3; j++) {
                    float v = o[mt][h][j];
                    v += __shfl_xor_sync(0xffffffffu, v, 1);
                    v += __shfl_xor_sync(0xffffffffu, v, 2);
                    o[mt][h][j] = v;
                }

        if (q < 3) {
            int j = q;
#pragma unroll
            for (int mt = 0; mt < 2; mt++)
#pragma unroll
                for (int h = 0; h < 2; h++) {
                    int row = pbase + mt * 16 + g + h * 8;
                    if (row < n) out[row * 3 + j] = o[mt][h][j];
                }
        }
        __syncwarp();
    }
}

extern "C" void kernel_launch(void* const* d_in, const int* in_sizes, int n_in,
                              void* d_out, int out_size) {
    const float* pos   = (const float*)d_in[0];
    const float* table = (const float*)d_in[1];
    const float* W1    = (const float*)d_in[2];
    const float* W2    = (const float*)d_in[3];
    const float* W3    = (const float*)d_in[4];
    float* out = (float*)d_out;
    int n = in_sizes[0] / 2;

    ngp_encode<<<(n + 255) / 256, 256>>>(pos, table, n);
    ngp_mlp<<<(n + CTA_PTS - 1) / CTA_PTS, 128>>>(W1, W2, W3, out, n);
}